// round 1
// baseline (speedup 1.0000x reference)
#include <cuda_runtime.h>
#include <math.h>

#define NB 15
#define NC 4096
#define BATCH 512
#define BCHUNKS 8
#define BPER (BATCH / BCHUNKS)   // 64 batch rows per chunk

// Scratch (allocation-free): partial batch sums + per-base stats
__device__ float  g_partial[NB * BCHUNKS * NC];   // [b][chunk][c]
__device__ double g_stats[2 * NB];                // [0..14]=sub_mean, [15..29]=sub_std

// ---------------------------------------------------------------------------
// Kernel 1: batch-dimension reduction (the HBM-bound part, reads all 125.8 MB)
// grid = (NC/1024, NB, BCHUNKS), block = 256, each thread owns one float4 of C
// ---------------------------------------------------------------------------
__global__ void __launch_bounds__(256) k1_batch_reduce(const float* __restrict__ in)
{
    const int b      = blockIdx.y;                         // base index 0..14
    const int c      = blockIdx.x * 1024 + threadIdx.x * 4; // channel
    const int batch0 = blockIdx.z * BPER;

    const size_t rowstride = (size_t)NB * NC;              // floats between batch rows
    const float* p = in + ((size_t)batch0 * NB + b) * NC + c;

    float4 a0 = make_float4(0.f, 0.f, 0.f, 0.f);
    float4 a1 = a0, a2 = a0, a3 = a0;

    #pragma unroll 4
    for (int i = 0; i < BPER; i += 4) {
        float4 v0 = *(const float4*)(p + (size_t)(i + 0) * rowstride);
        float4 v1 = *(const float4*)(p + (size_t)(i + 1) * rowstride);
        float4 v2 = *(const float4*)(p + (size_t)(i + 2) * rowstride);
        float4 v3 = *(const float4*)(p + (size_t)(i + 3) * rowstride);
        a0.x += v0.x; a0.y += v0.y; a0.z += v0.z; a0.w += v0.w;
        a1.x += v1.x; a1.y += v1.y; a1.z += v1.z; a1.w += v1.w;
        a2.x += v2.x; a2.y += v2.y; a2.z += v2.z; a2.w += v2.w;
        a3.x += v3.x; a3.y += v3.y; a3.z += v3.z; a3.w += v3.w;
    }

    float4 acc;
    acc.x = (a0.x + a1.x) + (a2.x + a3.x);
    acc.y = (a0.y + a1.y) + (a2.y + a3.y);
    acc.z = (a0.z + a1.z) + (a2.z + a3.z);
    acc.w = (a0.w + a1.w) + (a2.w + a3.w);

    *(float4*)&g_partial[((b * BCHUNKS + blockIdx.z) * NC) + c] = acc;
}

// ---------------------------------------------------------------------------
// Kernel 2: finish batch reduction, compute per-base mean & std(ddof=1) over C
// grid = NB, block = 256
// ---------------------------------------------------------------------------
__global__ void __launch_bounds__(256) k2_stats()
{
    const int b = blockIdx.x;

    double s = 0.0, s2 = 0.0;
    for (int c = threadIdx.x * 4; c < NC; c += 256 * 4) {
        float4 t = make_float4(0.f, 0.f, 0.f, 0.f);
        #pragma unroll
        for (int p = 0; p < BCHUNKS; p++) {
            float4 v = *(const float4*)&g_partial[(b * BCHUNKS + p) * NC + c];
            t.x += v.x; t.y += v.y; t.z += v.z; t.w += v.w;
        }
        double m;
        m = (double)t.x / (double)BATCH; s += m; s2 += m * m;
        m = (double)t.y / (double)BATCH; s += m; s2 += m * m;
        m = (double)t.z / (double)BATCH; s += m; s2 += m * m;
        m = (double)t.w / (double)BATCH; s += m; s2 += m * m;
    }

    __shared__ double shs[256], shs2[256];
    shs[threadIdx.x]  = s;
    shs2[threadIdx.x] = s2;
    __syncthreads();
    for (int off = 128; off > 0; off >>= 1) {
        if (threadIdx.x < off) {
            shs[threadIdx.x]  += shs[threadIdx.x + off];
            shs2[threadIdx.x] += shs2[threadIdx.x + off];
        }
        __syncthreads();
    }

    if (threadIdx.x == 0) {
        double sum   = shs[0];
        double sumsq = shs2[0];
        double mean  = sum / (double)NC;
        double var   = (sumsq - sum * sum / (double)NC) / (double)(NC - 1);
        if (var < 0.0) var = 0.0;
        g_stats[b]      = mean;        // sub_mean[b]
        g_stats[NB + b] = sqrt(var);   // sub_std[b], ddof=1
    }
}

// ---------------------------------------------------------------------------
// Kernel 3: group statistics + final loss (15 scalars -> 1 scalar)
// ---------------------------------------------------------------------------
__global__ void k3_loss(float* __restrict__ out)
{
    // SAME_IDS groups are contiguous: [0,3) [3,5) [5,6) [6,10) [10,12) [12,15)
    const int starts[7] = {0, 3, 5, 6, 10, 12, 15};
    const int G = 6;

    double ss[6], meanv[6], mean_sum[6];

    for (int g = 0; g < G; g++) {
        const int s0 = starts[g], s1 = starts[g + 1];
        const int n = s1 - s0;
        if (n == 1) {
            ss[g]       = g_stats[NB + s0];
            mean_sum[g] = g_stats[s0];
            meanv[g]    = g_stats[s0];
        } else {
            double ms = 0.0, mm = 0.0;
            for (int i = s0; i < s1; i++) { ms += g_stats[NB + i]; mm += g_stats[i]; }
            ms /= n; mm /= n;
            double vs = 0.0, vm = 0.0;
            for (int i = s0; i < s1; i++) {
                double d = g_stats[NB + i] - ms; vs += d * d;
                double e = g_stats[i]      - mm; vm += e * e;
            }
            ss[g]       = sqrt(vs / (double)(n - 1));
            mean_sum[g] = sqrt(vm / (double)(n - 1));
            meanv[g]    = mm;
        }
    }

    double loss = 0.0;
    for (int i = 0; i < G; i++) {
        double subloss = (double)5e-5f;
        for (int j = i + 1; j < G; j++) {
            double d1 = ss[i] - ss[j];
            double d2 = meanv[i] - meanv[j];
            subloss += exp(d1 * d1) + exp(d2 * d2);   // MEAN_STD = 1.0
        }
        loss += log(1.0 + mean_sum[i] / (subloss + mean_sum[i]));
    }

    *out = (float)loss;
}

// ---------------------------------------------------------------------------
extern "C" void kernel_launch(void* const* d_in, const int* in_sizes, int n_in,
                              void* d_out, int out_size)
{
    const float* meta1 = (const float*)d_in[0];

    dim3 g1(NC / 1024, NB, BCHUNKS);   // (4, 15, 8) = 480 CTAs
    k1_batch_reduce<<<g1, 256>>>(meta1);
    k2_stats<<<NB, 256>>>();
    k3_loss<<<1, 1>>>((float*)d_out);
}

// round 2
// speedup vs baseline: 1.5364x; 1.5364x over previous
#include <cuda_runtime.h>
#include <math.h>

#define NB 15
#define NC 4096
#define BATCH 512
#define ZCH 37            // batch chunks: 4*15*37 = 2220 CTAs = 3 exact waves @ occ 5

// Scratch (allocation-free)
__device__ float        g_partial[NB * ZCH * NC];   // [b][z][c]
__device__ double       g_stats[2 * NB];            // [0..14]=sub_mean, [15..29]=sub_std
__device__ unsigned int g_ctr;                      // zero-init; reset by last block

// ---------------------------------------------------------------------------
// Kernel 1: batch-dimension reduction (HBM-bound, reads all 125.8 MB)
// grid = (NC/1024, NB, ZCH), block = 256, each thread owns one float4 of C
// ---------------------------------------------------------------------------
__global__ void __launch_bounds__(256) k1_batch_reduce(const float* __restrict__ in)
{
    const int b = blockIdx.y;
    const int c = blockIdx.x * 1024 + threadIdx.x * 4;
    const int z = blockIdx.z;

    // uneven split of 512 rows into 37 chunks (31 chunks of 14, 6 of 13)
    const int r0 = (z * BATCH) / ZCH;
    const int r1 = ((z + 1) * BATCH) / ZCH;
    const int n  = r1 - r0;

    const size_t rowstride = (size_t)NB * NC;
    const float* p = in + ((size_t)r0 * NB + b) * NC + c;

    float4 a0 = make_float4(0.f, 0.f, 0.f, 0.f);
    float4 a1 = a0, a2 = a0, a3 = a0;

    int i = 0;
    for (; i + 3 < n; i += 4) {
        float4 v0 = *(const float4*)(p + (size_t)(i + 0) * rowstride);
        float4 v1 = *(const float4*)(p + (size_t)(i + 1) * rowstride);
        float4 v2 = *(const float4*)(p + (size_t)(i + 2) * rowstride);
        float4 v3 = *(const float4*)(p + (size_t)(i + 3) * rowstride);
        a0.x += v0.x; a0.y += v0.y; a0.z += v0.z; a0.w += v0.w;
        a1.x += v1.x; a1.y += v1.y; a1.z += v1.z; a1.w += v1.w;
        a2.x += v2.x; a2.y += v2.y; a2.z += v2.z; a2.w += v2.w;
        a3.x += v3.x; a3.y += v3.y; a3.z += v3.z; a3.w += v3.w;
    }
    for (; i < n; i++) {
        float4 v = *(const float4*)(p + (size_t)i * rowstride);
        a0.x += v.x; a0.y += v.y; a0.z += v.z; a0.w += v.w;
    }

    float4 acc;
    acc.x = (a0.x + a1.x) + (a2.x + a3.x);
    acc.y = (a0.y + a1.y) + (a2.y + a3.y);
    acc.z = (a0.z + a1.z) + (a2.z + a3.z);
    acc.w = (a0.w + a1.w) + (a2.w + a3.w);

    *(float4*)&g_partial[((b * ZCH + z) * NC) + c] = acc;
}

// ---------------------------------------------------------------------------
// Kernel 2 (fused): per-base mean & std(ddof=1) over C; the LAST block to
// finish computes the final loss with warp-parallel double transcendentals.
// grid = NB, block = 256
// ---------------------------------------------------------------------------
__global__ void __launch_bounds__(256) k2_stats_and_loss(float* __restrict__ out)
{
    const int b = blockIdx.x;

    double s = 0.0, s2 = 0.0;
    for (int c = threadIdx.x * 4; c < NC; c += 256 * 4) {
        float4 t = make_float4(0.f, 0.f, 0.f, 0.f);
        #pragma unroll
        for (int p = 0; p < ZCH; p++) {
            float4 v = *(const float4*)&g_partial[(b * ZCH + p) * NC + c];
            t.x += v.x; t.y += v.y; t.z += v.z; t.w += v.w;
        }
        double m;
        m = (double)t.x / (double)BATCH; s += m; s2 += m * m;
        m = (double)t.y / (double)BATCH; s += m; s2 += m * m;
        m = (double)t.z / (double)BATCH; s += m; s2 += m * m;
        m = (double)t.w / (double)BATCH; s += m; s2 += m * m;
    }

    __shared__ double shs[256], shs2[256];
    shs[threadIdx.x]  = s;
    shs2[threadIdx.x] = s2;
    __syncthreads();
    for (int off = 128; off > 0; off >>= 1) {
        if (threadIdx.x < off) {
            shs[threadIdx.x]  += shs[threadIdx.x + off];
            shs2[threadIdx.x] += shs2[threadIdx.x + off];
        }
        __syncthreads();
    }

    __shared__ int sh_last;
    if (threadIdx.x == 0) {
        double sum   = shs[0];
        double sumsq = shs2[0];
        double mean  = sum / (double)NC;
        double var   = (sumsq - sum * sum / (double)NC) / (double)(NC - 1);
        if (var < 0.0) var = 0.0;
        g_stats[b]      = mean;
        g_stats[NB + b] = sqrt(var);
        __threadfence();
        unsigned int old = atomicAdd(&g_ctr, 1u);
        sh_last = (old == NB - 1) ? 1 : 0;
    }
    __syncthreads();
    if (!sh_last || threadIdx.x >= 32) return;

    // ---- last block, warp 0: final loss, warp-parallel double math ----
    __threadfence();   // acquire: make all blocks' g_stats visible

    const int lane = threadIdx.x;
    // groups: [0,3) [3,5) [5,6) [6,10) [10,12) [12,15)
    const int starts[7] = {0, 3, 5, 6, 10, 12, 15};
    const int G = 6;
    // 15 ordered pairs (i<j) of 6 groups
    const int pi[15] = {0,0,0,0,0, 1,1,1,1, 2,2,2, 3,3, 4};
    const int pj[15] = {1,2,3,4,5, 2,3,4,5, 3,4,5, 4,5, 5};

    __shared__ double sh_ss[6], sh_mn[6], sh_msum[6], sh_pair[15], sh_lt[6];

    if (lane < G) {
        const int s0 = starts[lane], s1 = starts[lane + 1];
        const int n = s1 - s0;
        if (n == 1) {
            sh_ss[lane]   = g_stats[NB + s0];
            sh_msum[lane] = g_stats[s0];
            sh_mn[lane]   = g_stats[s0];
        } else {
            double ms = 0.0, mm = 0.0;
            for (int i = s0; i < s1; i++) { ms += g_stats[NB + i]; mm += g_stats[i]; }
            ms /= n; mm /= n;
            double vs = 0.0, vm = 0.0;
            for (int i = s0; i < s1; i++) {
                double d = g_stats[NB + i] - ms; vs += d * d;
                double e = g_stats[i]      - mm; vm += e * e;
            }
            sh_ss[lane]   = sqrt(vs / (double)(n - 1));
            sh_msum[lane] = sqrt(vm / (double)(n - 1));
            sh_mn[lane]   = mm;
        }
    }
    __syncwarp();

    if (lane < 15) {
        double d1 = sh_ss[pi[lane]] - sh_ss[pj[lane]];
        double d2 = sh_mn[pi[lane]] - sh_mn[pj[lane]];
        sh_pair[lane] = exp(d1 * d1) + exp(d2 * d2);   // MEAN_STD = 1.0
    }
    __syncwarp();

    if (lane < G) {
        double subloss = (double)5e-5f;
        #pragma unroll
        for (int p = 0; p < 15; p++)
            if (pi[p] == lane) subloss += sh_pair[p];
        sh_lt[lane] = log(1.0 + sh_msum[lane] / (subloss + sh_msum[lane]));
    }
    __syncwarp();

    if (lane == 0) {
        double loss = 0.0;
        #pragma unroll
        for (int g = 0; g < G; g++) loss += sh_lt[g];
        out[0] = (float)loss;
        g_ctr = 0;   // reset for next graph replay (deterministic)
    }
}

// ---------------------------------------------------------------------------
extern "C" void kernel_launch(void* const* d_in, const int* in_sizes, int n_in,
                              void* d_out, int out_size)
{
    const float* meta1 = (const float*)d_in[0];

    dim3 g1(NC / 1024, NB, ZCH);   // (4, 15, 37) = 2220 CTAs = 3 full waves
    k1_batch_reduce<<<g1, 256>>>(meta1);
    k2_stats_and_loss<<<NB, 256>>>((float*)d_out);
}

// round 3
// speedup vs baseline: 1.8734x; 1.2193x over previous
#include <cuda_runtime.h>
#include <math.h>

#define NB 15
#define NC 4096
#define BATCH 512
#define ZCH 37            // batch chunks in k1: 4*15*37 = 2220 CTAs = 3 exact waves
#define CCH 8             // channel chunks in k2: 8*15 = 120 blocks

// Scratch (allocation-free)
__device__ float        g_partial[NB * ZCH * NC];   // [b][z][c]
__device__ double2      g_bpart[NB * CCH];          // per (b, cchunk): {sum m, sum m^2}
__device__ unsigned int g_ctr;                      // zero-init; reset by last block

// ---------------------------------------------------------------------------
// Kernel 1: batch-dimension reduction (HBM-bound, reads all 125.8 MB)
// grid = (NC/1024, NB, ZCH), block = 256, each thread owns one float4 of C
// ---------------------------------------------------------------------------
__global__ void __launch_bounds__(256) k1_batch_reduce(const float* __restrict__ in)
{
    const int b = blockIdx.y;
    const int c = blockIdx.x * 1024 + threadIdx.x * 4;
    const int z = blockIdx.z;

    // uneven split of 512 rows into 37 chunks (31 chunks of 14, 6 of 13)
    const int r0 = (z * BATCH) / ZCH;
    const int r1 = ((z + 1) * BATCH) / ZCH;
    const int n  = r1 - r0;

    const size_t rowstride = (size_t)NB * NC;
    const float* p = in + ((size_t)r0 * NB + b) * NC + c;

    float4 a0 = make_float4(0.f, 0.f, 0.f, 0.f);
    float4 a1 = a0, a2 = a0, a3 = a0;

    int i = 0;
    for (; i + 3 < n; i += 4) {
        float4 v0 = *(const float4*)(p + (size_t)(i + 0) * rowstride);
        float4 v1 = *(const float4*)(p + (size_t)(i + 1) * rowstride);
        float4 v2 = *(const float4*)(p + (size_t)(i + 2) * rowstride);
        float4 v3 = *(const float4*)(p + (size_t)(i + 3) * rowstride);
        a0.x += v0.x; a0.y += v0.y; a0.z += v0.z; a0.w += v0.w;
        a1.x += v1.x; a1.y += v1.y; a1.z += v1.z; a1.w += v1.w;
        a2.x += v2.x; a2.y += v2.y; a2.z += v2.z; a2.w += v2.w;
        a3.x += v3.x; a3.y += v3.y; a3.z += v3.z; a3.w += v3.w;
    }
    for (; i < n; i++) {
        float4 v = *(const float4*)(p + (size_t)i * rowstride);
        a0.x += v.x; a0.y += v.y; a0.z += v.z; a0.w += v.w;
    }

    float4 acc;
    acc.x = (a0.x + a1.x) + (a2.x + a3.x);
    acc.y = (a0.y + a1.y) + (a2.y + a3.y);
    acc.z = (a0.z + a1.z) + (a2.z + a3.z);
    acc.w = (a0.w + a1.w) + (a2.w + a3.w);

    *(float4*)&g_partial[((b * ZCH + z) * NC) + c] = acc;
}

// ---------------------------------------------------------------------------
// Kernel 2 (fused, parallel): 120 blocks. Each block reduces the 37 z-partials
// for 512 channels of one base (L2-resident) and emits (sum m, sum m^2).
// Last block to finish computes mean/std per base + the final loss.
// grid = (CCH, NB), block = 128
// ---------------------------------------------------------------------------
__global__ void __launch_bounds__(128) k2_stats_and_loss(float* __restrict__ out)
{
    const int b  = blockIdx.y;
    const int cc = blockIdx.x;
    const int c  = cc * 512 + threadIdx.x * 4;   // 128 threads * float4 = 512 channels

    const float* base = &g_partial[(size_t)(b * ZCH) * NC + c];

    float4 t0 = make_float4(0.f, 0.f, 0.f, 0.f);
    float4 t1 = t0;
    #pragma unroll
    for (int z = 0; z < ZCH; z += 2) {
        float4 v0 = *(const float4*)(base + (size_t)z * NC);
        t0.x += v0.x; t0.y += v0.y; t0.z += v0.z; t0.w += v0.w;
        if (z + 1 < ZCH) {
            float4 v1 = *(const float4*)(base + (size_t)(z + 1) * NC);
            t1.x += v1.x; t1.y += v1.y; t1.z += v1.z; t1.w += v1.w;
        }
    }
    float4 t;
    t.x = t0.x + t1.x; t.y = t0.y + t1.y; t.z = t0.z + t1.z; t.w = t0.w + t1.w;

    double s = 0.0, s2 = 0.0, m;
    m = (double)t.x / (double)BATCH; s += m; s2 += m * m;
    m = (double)t.y / (double)BATCH; s += m; s2 += m * m;
    m = (double)t.z / (double)BATCH; s += m; s2 += m * m;
    m = (double)t.w / (double)BATCH; s += m; s2 += m * m;

    __shared__ double shs[128], shs2[128];
    shs[threadIdx.x]  = s;
    shs2[threadIdx.x] = s2;
    __syncthreads();
    for (int off = 64; off > 0; off >>= 1) {
        if (threadIdx.x < off) {
            shs[threadIdx.x]  += shs[threadIdx.x + off];
            shs2[threadIdx.x] += shs2[threadIdx.x + off];
        }
        __syncthreads();
    }

    __shared__ int sh_last;
    if (threadIdx.x == 0) {
        g_bpart[b * CCH + cc] = make_double2(shs[0], shs2[0]);
        __threadfence();
        unsigned int old = atomicAdd(&g_ctr, 1u);
        sh_last = (old == NB * CCH - 1) ? 1 : 0;
    }
    __syncthreads();
    if (!sh_last || threadIdx.x >= 32) return;

    // ---- last block, warp 0: per-base stats + final loss ----
    __threadfence();   // acquire all blocks' g_bpart

    const int lane = threadIdx.x;
    __shared__ double sh_mean[NB], sh_std[NB];

    if (lane < NB) {
        double sum = 0.0, sumsq = 0.0;
        #pragma unroll
        for (int p = 0; p < CCH; p++) {
            double2 v = g_bpart[lane * CCH + p];
            sum += v.x; sumsq += v.y;
        }
        double mean = sum / (double)NC;
        double var  = (sumsq - sum * sum / (double)NC) / (double)(NC - 1);
        if (var < 0.0) var = 0.0;
        sh_mean[lane] = mean;
        sh_std[lane]  = sqrt(var);
    }
    __syncwarp();

    // groups: [0,3) [3,5) [5,6) [6,10) [10,12) [12,15)
    const int starts[7] = {0, 3, 5, 6, 10, 12, 15};
    const int G = 6;
    const int pi[15] = {0,0,0,0,0, 1,1,1,1, 2,2,2, 3,3, 4};
    const int pj[15] = {1,2,3,4,5, 2,3,4,5, 3,4,5, 4,5, 5};

    __shared__ double sh_ss[6], sh_mn[6], sh_msum[6], sh_pair[15], sh_lt[6];

    if (lane < G) {
        const int s0 = starts[lane], s1 = starts[lane + 1];
        const int n = s1 - s0;
        if (n == 1) {
            sh_ss[lane]   = sh_std[s0];
            sh_msum[lane] = sh_mean[s0];
            sh_mn[lane]   = sh_mean[s0];
        } else {
            double ms = 0.0, mm = 0.0;
            for (int i = s0; i < s1; i++) { ms += sh_std[i]; mm += sh_mean[i]; }
            ms /= n; mm /= n;
            double vs = 0.0, vm = 0.0;
            for (int i = s0; i < s1; i++) {
                double d = sh_std[i]  - ms; vs += d * d;
                double e = sh_mean[i] - mm; vm += e * e;
            }
            sh_ss[lane]   = sqrt(vs / (double)(n - 1));
            sh_msum[lane] = sqrt(vm / (double)(n - 1));
            sh_mn[lane]   = mm;
        }
    }
    __syncwarp();

    if (lane < 15) {
        double d1 = sh_ss[pi[lane]] - sh_ss[pj[lane]];
        double d2 = sh_mn[pi[lane]] - sh_mn[pj[lane]];
        sh_pair[lane] = exp(d1 * d1) + exp(d2 * d2);   // MEAN_STD = 1.0
    }
    __syncwarp();

    if (lane < G) {
        double subloss = (double)5e-5f;
        #pragma unroll
        for (int p = 0; p < 15; p++)
            if (pi[p] == lane) subloss += sh_pair[p];
        sh_lt[lane] = log(1.0 + sh_msum[lane] / (subloss + sh_msum[lane]));
    }
    __syncwarp();

    if (lane == 0) {
        double loss = 0.0;
        #pragma unroll
        for (int g = 0; g < G; g++) loss += sh_lt[g];
        out[0] = (float)loss;
        g_ctr = 0;   // reset for next graph replay
    }
}

// ---------------------------------------------------------------------------
extern "C" void kernel_launch(void* const* d_in, const int* in_sizes, int n_in,
                              void* d_out, int out_size)
{
    const float* meta1 = (const float*)d_in[0];

    dim3 g1(NC / 1024, NB, ZCH);   // (4, 15, 37) = 2220 CTAs = 3 full waves
    k1_batch_reduce<<<g1, 256>>>(meta1);

    dim3 g2(CCH, NB);              // 120 blocks
    k2_stats_and_loss<<<g2, 128>>>((float*)d_out);
}

// round 4
// speedup vs baseline: 2.1882x; 1.1680x over previous
#include <cuda_runtime.h>
#include <math.h>

#define NB 15
#define NC 4096
#define BATCH 512
#define ZCH 37            // batch chunks in k1: 4*15*37 = 2220 CTAs = 3 exact waves
#define CCH 8             // channel chunks in k2: 8*15 = 120 blocks

// Scratch (allocation-free)
__device__ float        g_partial[NB * ZCH * NC];   // [b][z][c]
__device__ float2       g_bpart[NB * CCH];          // per (b, cchunk): {sum m, sum m^2}
__device__ unsigned int g_ctr;                      // zero-init; reset by last block

// ---------------------------------------------------------------------------
// Kernel 1: batch-dimension reduction (HBM-bound, reads all 125.8 MB)
// grid = (NC/1024, NB, ZCH), block = 256, each thread owns one float4 of C
// ---------------------------------------------------------------------------
__global__ void __launch_bounds__(256) k1_batch_reduce(const float* __restrict__ in)
{
    const int b = blockIdx.y;
    const int c = blockIdx.x * 1024 + threadIdx.x * 4;
    const int z = blockIdx.z;

    // uneven split of 512 rows into 37 chunks (31 chunks of 14, 6 of 13)
    const int r0 = (z * BATCH) / ZCH;
    const int r1 = ((z + 1) * BATCH) / ZCH;
    const int n  = r1 - r0;

    const size_t rowstride = (size_t)NB * NC;
    const float* p = in + ((size_t)r0 * NB + b) * NC + c;

    float4 a0 = make_float4(0.f, 0.f, 0.f, 0.f);
    float4 a1 = a0, a2 = a0, a3 = a0;

    int i = 0;
    for (; i + 3 < n; i += 4) {
        float4 v0 = *(const float4*)(p + (size_t)(i + 0) * rowstride);
        float4 v1 = *(const float4*)(p + (size_t)(i + 1) * rowstride);
        float4 v2 = *(const float4*)(p + (size_t)(i + 2) * rowstride);
        float4 v3 = *(const float4*)(p + (size_t)(i + 3) * rowstride);
        a0.x += v0.x; a0.y += v0.y; a0.z += v0.z; a0.w += v0.w;
        a1.x += v1.x; a1.y += v1.y; a1.z += v1.z; a1.w += v1.w;
        a2.x += v2.x; a2.y += v2.y; a2.z += v2.z; a2.w += v2.w;
        a3.x += v3.x; a3.y += v3.y; a3.z += v3.z; a3.w += v3.w;
    }
    for (; i < n; i++) {
        float4 v = *(const float4*)(p + (size_t)i * rowstride);
        a0.x += v.x; a0.y += v.y; a0.z += v.z; a0.w += v.w;
    }

    float4 acc;
    acc.x = (a0.x + a1.x) + (a2.x + a3.x);
    acc.y = (a0.y + a1.y) + (a2.y + a3.y);
    acc.z = (a0.z + a1.z) + (a2.z + a3.z);
    acc.w = (a0.w + a1.w) + (a2.w + a3.w);

    *(float4*)&g_partial[((b * ZCH + z) * NC) + c] = acc;
}

// ---------------------------------------------------------------------------
// Kernel 2 (fused, fp32): 120 blocks. Each block reduces the 37 z-partials for
// 512 channels of one base (L2-resident) -> (sum m, sum m^2) in fp32.
// Last block to finish computes mean/std per base + the final loss in fp32.
// grid = (CCH, NB), block = 128
// ---------------------------------------------------------------------------
__global__ void __launch_bounds__(128) k2_stats_and_loss(float* __restrict__ out)
{
    const int b  = blockIdx.y;
    const int cc = blockIdx.x;
    const int c  = cc * 512 + threadIdx.x * 4;   // 128 threads * float4 = 512 channels

    const float* base = &g_partial[(size_t)(b * ZCH) * NC + c];

    float4 t0 = make_float4(0.f, 0.f, 0.f, 0.f);
    float4 t1 = t0;
    #pragma unroll
    for (int z = 0; z < ZCH; z += 2) {
        float4 v0 = *(const float4*)(base + (size_t)z * NC);
        t0.x += v0.x; t0.y += v0.y; t0.z += v0.z; t0.w += v0.w;
        if (z + 1 < ZCH) {
            float4 v1 = *(const float4*)(base + (size_t)(z + 1) * NC);
            t1.x += v1.x; t1.y += v1.y; t1.z += v1.z; t1.w += v1.w;
        }
    }

    const float inv_batch = 1.0f / (float)BATCH;   // exact (power of two)
    float m0 = (t0.x + t1.x) * inv_batch;
    float m1 = (t0.y + t1.y) * inv_batch;
    float m2 = (t0.z + t1.z) * inv_batch;
    float m3 = (t0.w + t1.w) * inv_batch;

    float s  = (m0 + m1) + (m2 + m3);
    float s2 = fmaf(m0, m0, m1 * m1) + fmaf(m2, m2, m3 * m3);

    // warp shuffle reduction, then 4 warp results via smem
    #pragma unroll
    for (int off = 16; off > 0; off >>= 1) {
        s  += __shfl_xor_sync(0xffffffffu, s,  off);
        s2 += __shfl_xor_sync(0xffffffffu, s2, off);
    }

    __shared__ float shs[4], shs2[4];
    const int wid  = threadIdx.x >> 5;
    const int lane = threadIdx.x & 31;
    if (lane == 0) { shs[wid] = s; shs2[wid] = s2; }
    __syncthreads();

    __shared__ int sh_last;
    if (threadIdx.x == 0) {
        float sum   = (shs[0]  + shs[1])  + (shs[2]  + shs[3]);
        float sumsq = (shs2[0] + shs2[1]) + (shs2[2] + shs2[3]);
        g_bpart[b * CCH + cc] = make_float2(sum, sumsq);
        __threadfence();
        unsigned int old = atomicAdd(&g_ctr, 1u);
        sh_last = (old == NB * CCH - 1) ? 1 : 0;
    }
    __syncthreads();
    if (!sh_last || threadIdx.x >= 32) return;

    // ---- last block, warp 0: per-base stats + final loss (all fp32) ----
    __threadfence();   // acquire all blocks' g_bpart

    const int l = threadIdx.x;
    __shared__ float sh_mean[NB], sh_std[NB];

    if (l < NB) {
        float sum = 0.f, sumsq = 0.f;
        #pragma unroll
        for (int p = 0; p < CCH; p++) {
            float2 v = g_bpart[l * CCH + p];
            sum += v.x; sumsq += v.y;
        }
        float mean = sum * (1.0f / (float)NC);            // exact scale
        float var  = (sumsq - sum * sum * (1.0f / (float)NC)) * (1.0f / (float)(NC - 1));
        if (var < 0.f) var = 0.f;
        sh_mean[l] = mean;
        sh_std[l]  = sqrtf(var);
    }
    __syncwarp();

    // groups: [0,3) [3,5) [5,6) [6,10) [10,12) [12,15)
    const int starts[7] = {0, 3, 5, 6, 10, 12, 15};
    const int G = 6;
    const int pi[15] = {0,0,0,0,0, 1,1,1,1, 2,2,2, 3,3, 4};
    const int pj[15] = {1,2,3,4,5, 2,3,4,5, 3,4,5, 4,5, 5};

    __shared__ float sh_ss[6], sh_mn[6], sh_msum[6], sh_pair[15], sh_lt[6];

    if (l < G) {
        const int s0 = starts[l], s1 = starts[l + 1];
        const int n = s1 - s0;
        if (n == 1) {
            sh_ss[l]   = sh_std[s0];
            sh_msum[l] = sh_mean[s0];
            sh_mn[l]   = sh_mean[s0];
        } else {
            float ms = 0.f, mm = 0.f;
            for (int i = s0; i < s1; i++) { ms += sh_std[i]; mm += sh_mean[i]; }
            ms /= (float)n; mm /= (float)n;
            float vs = 0.f, vm = 0.f;
            for (int i = s0; i < s1; i++) {
                float d = sh_std[i]  - ms; vs = fmaf(d, d, vs);
                float e = sh_mean[i] - mm; vm = fmaf(e, e, vm);
            }
            sh_ss[l]   = sqrtf(vs / (float)(n - 1));
            sh_msum[l] = sqrtf(vm / (float)(n - 1));
            sh_mn[l]   = mm;
        }
    }
    __syncwarp();

    if (l < 15) {
        float d1 = sh_ss[pi[l]] - sh_ss[pj[l]];
        float d2 = sh_mn[pi[l]] - sh_mn[pj[l]];
        sh_pair[l] = expf(d1 * d1) + expf(d2 * d2);   // MEAN_STD = 1.0
    }
    __syncwarp();

    if (l < G) {
        float subloss = 5e-5f;
        #pragma unroll
        for (int p = 0; p < 15; p++)
            if (pi[p] == l) subloss += sh_pair[p];
        sh_lt[l] = logf(1.0f + sh_msum[l] / (subloss + sh_msum[l]));
    }
    __syncwarp();

    if (l == 0) {
        float loss = 0.f;
        #pragma unroll
        for (int g = 0; g < G; g++) loss += sh_lt[g];
        out[0] = loss;
        g_ctr = 0;   // reset for next graph replay
    }
}

// ---------------------------------------------------------------------------
extern "C" void kernel_launch(void* const* d_in, const int* in_sizes, int n_in,
                              void* d_out, int out_size)
{
    const float* meta1 = (const float*)d_in[0];

    dim3 g1(NC / 1024, NB, ZCH);   // (4, 15, 37) = 2220 CTAs = 3 full waves
    k1_batch_reduce<<<g1, 256>>>(meta1);

    dim3 g2(CCH, NB);              // 120 blocks
    k2_stats_and_loss<<<g2, 128>>>((float*)d_out);
}

// round 5
// speedup vs baseline: 2.2913x; 1.0471x over previous
#include <cuda_runtime.h>
#include <math.h>

#define NB 15
#define NC 4096
#define BATCH 512
#define ZCH 37            // batch chunks in k1: 4*15*37 = 2220 CTAs = 3 exact waves
#define CC2 16            // vec-col chunks in k2: 16*15 = 240 blocks

// Scratch (allocation-free)
__device__ float        g_partial[NB * ZCH * NC];   // [b][z][c]
__device__ float2       g_bpart[NB * CC2];          // per (b, chunk): {sum m, sum m^2}
__device__ unsigned int g_ctr;                      // zero-init; reset by last block

// ---------------------------------------------------------------------------
// Kernel 1: batch-dimension reduction (HBM-bound, reads all 125.8 MB)
// grid = (NC/1024, NB, ZCH), block = 256, each thread owns one float4 of C
// ---------------------------------------------------------------------------
__global__ void __launch_bounds__(256) k1_batch_reduce(const float* __restrict__ in)
{
    const int b = blockIdx.y;
    const int c = blockIdx.x * 1024 + threadIdx.x * 4;
    const int z = blockIdx.z;

    // uneven split of 512 rows into 37 chunks (31 chunks of 14, 6 of 13)
    const int r0 = (z * BATCH) / ZCH;
    const int r1 = ((z + 1) * BATCH) / ZCH;
    const int n  = r1 - r0;

    const size_t rowstride = (size_t)NB * NC;
    const float* p = in + ((size_t)r0 * NB + b) * NC + c;

    float4 a0 = make_float4(0.f, 0.f, 0.f, 0.f);
    float4 a1 = a0, a2 = a0, a3 = a0;

    int i = 0;
    for (; i + 3 < n; i += 4) {
        float4 v0 = *(const float4*)(p + (size_t)(i + 0) * rowstride);
        float4 v1 = *(const float4*)(p + (size_t)(i + 1) * rowstride);
        float4 v2 = *(const float4*)(p + (size_t)(i + 2) * rowstride);
        float4 v3 = *(const float4*)(p + (size_t)(i + 3) * rowstride);
        a0.x += v0.x; a0.y += v0.y; a0.z += v0.z; a0.w += v0.w;
        a1.x += v1.x; a1.y += v1.y; a1.z += v1.z; a1.w += v1.w;
        a2.x += v2.x; a2.y += v2.y; a2.z += v2.z; a2.w += v2.w;
        a3.x += v3.x; a3.y += v3.y; a3.z += v3.z; a3.w += v3.w;
    }
    for (; i < n; i++) {
        float4 v = *(const float4*)(p + (size_t)i * rowstride);
        a0.x += v.x; a0.y += v.y; a0.z += v.z; a0.w += v.w;
    }

    float4 acc;
    acc.x = (a0.x + a1.x) + (a2.x + a3.x);
    acc.y = (a0.y + a1.y) + (a2.y + a3.y);
    acc.z = (a0.z + a1.z) + (a2.z + a3.z);
    acc.w = (a0.w + a1.w) + (a2.w + a3.w);

    *(float4*)&g_partial[((b * ZCH + z) * NC) + c] = acc;
}

// ---------------------------------------------------------------------------
// Kernel 2 (fused, fp32): grid (CC2, NB) = 240 blocks of 256 threads.
// Threads = 64 c-lanes x 4 z-slices; each thread loads 9-10 float4 partials
// (L2-resident), smem combines z-slices, block reduces (sum m, sum m^2).
// Last block to finish computes per-base mean/std + the final loss.
// ---------------------------------------------------------------------------
__global__ void __launch_bounds__(256) k2_stats_and_loss(float* __restrict__ out)
{
    const int b     = blockIdx.y;
    const int cc    = blockIdx.x;
    const int tid   = threadIdx.x;
    const int clane = tid & 63;          // 64 vec-columns per block
    const int zsl   = tid >> 6;          // 4 z-slices

    const int c  = (cc * 64 + clane) * 4;       // float index
    const int z0 = (zsl * ZCH) / 4;              // 0,9,18,27
    const int z1 = ((zsl + 1) * ZCH) / 4;        // 9,18,27,37

    const float* base = &g_partial[(size_t)(b * ZCH + z0) * NC + c];

    float4 t0 = make_float4(0.f, 0.f, 0.f, 0.f);
    float4 t1 = t0;
    const int n = z1 - z0;                       // 9 or 10
    int i = 0;
    for (; i + 1 < n; i += 2) {
        float4 v0 = *(const float4*)(base + (size_t)(i + 0) * NC);
        float4 v1 = *(const float4*)(base + (size_t)(i + 1) * NC);
        t0.x += v0.x; t0.y += v0.y; t0.z += v0.z; t0.w += v0.w;
        t1.x += v1.x; t1.y += v1.y; t1.z += v1.z; t1.w += v1.w;
    }
    if (i < n) {
        float4 v = *(const float4*)(base + (size_t)i * NC);
        t0.x += v.x; t0.y += v.y; t0.z += v.z; t0.w += v.w;
    }
    float4 t;
    t.x = t0.x + t1.x; t.y = t0.y + t1.y; t.z = t0.z + t1.z; t.w = t0.w + t1.w;

    __shared__ float4 shz[256];
    shz[tid] = t;
    __syncthreads();

    float s = 0.f, s2 = 0.f;
    if (zsl == 0) {
        float4 u1 = shz[tid + 64], u2 = shz[tid + 128], u3 = shz[tid + 192];
        t.x = (t.x + u1.x) + (u2.x + u3.x);
        t.y = (t.y + u1.y) + (u2.y + u3.y);
        t.z = (t.z + u1.z) + (u2.z + u3.z);
        t.w = (t.w + u1.w) + (u2.w + u3.w);

        const float inv_batch = 1.0f / (float)BATCH;  // exact
        float m0 = t.x * inv_batch;
        float m1 = t.y * inv_batch;
        float m2 = t.z * inv_batch;
        float m3 = t.w * inv_batch;

        s  = (m0 + m1) + (m2 + m3);
        s2 = fmaf(m0, m0, m1 * m1) + fmaf(m2, m2, m3 * m3);

        // warps 0 and 1 are fully covered by tid<64 -> full-warp shuffles OK
        #pragma unroll
        for (int off = 16; off > 0; off >>= 1) {
            s  += __shfl_xor_sync(0xffffffffu, s,  off);
            s2 += __shfl_xor_sync(0xffffffffu, s2, off);
        }
    }

    __shared__ float rs[2], rs2[2];
    if (tid < 64 && (tid & 31) == 0) { rs[tid >> 5] = s; rs2[tid >> 5] = s2; }
    __syncthreads();

    __shared__ int sh_last;
    if (tid == 0) {
        g_bpart[b * CC2 + cc] = make_float2(rs[0] + rs[1], rs2[0] + rs2[1]);
        __threadfence();
        unsigned int old = atomicAdd(&g_ctr, 1u);
        sh_last = (old == NB * CC2 - 1) ? 1 : 0;
    }
    __syncthreads();
    if (!sh_last || tid >= 32) return;

    // ---- last block, warp 0: per-base stats + final loss (all fp32) ----
    __threadfence();   // acquire all blocks' g_bpart

    const int l = tid;
    __shared__ float sh_mean[NB], sh_std[NB];

    if (l < NB) {
        float sum = 0.f, sumsq = 0.f;
        #pragma unroll
        for (int p = 0; p < CC2; p++) {
            float2 v = g_bpart[l * CC2 + p];
            sum += v.x; sumsq += v.y;
        }
        float mean = sum * (1.0f / (float)NC);            // exact scale
        float var  = (sumsq - sum * sum * (1.0f / (float)NC)) * (1.0f / (float)(NC - 1));
        if (var < 0.f) var = 0.f;
        sh_mean[l] = mean;
        sh_std[l]  = sqrtf(var);
    }
    __syncwarp();

    // groups: [0,3) [3,5) [5,6) [6,10) [10,12) [12,15)
    const int starts[7] = {0, 3, 5, 6, 10, 12, 15};
    const int G = 6;
    const int pi[15] = {0,0,0,0,0, 1,1,1,1, 2,2,2, 3,3, 4};
    const int pj[15] = {1,2,3,4,5, 2,3,4,5, 3,4,5, 4,5, 5};

    __shared__ float sh_ss[6], sh_mn[6], sh_msum[6], sh_pair[15], sh_lt[6];

    if (l < G) {
        const int s0 = starts[l], s1 = starts[l + 1];
        const int ng = s1 - s0;
        if (ng == 1) {
            sh_ss[l]   = sh_std[s0];
            sh_msum[l] = sh_mean[s0];
            sh_mn[l]   = sh_mean[s0];
        } else {
            float ms = 0.f, mm = 0.f;
            for (int k = s0; k < s1; k++) { ms += sh_std[k]; mm += sh_mean[k]; }
            ms /= (float)ng; mm /= (float)ng;
            float vs = 0.f, vm = 0.f;
            for (int k = s0; k < s1; k++) {
                float d = sh_std[k]  - ms; vs = fmaf(d, d, vs);
                float e = sh_mean[k] - mm; vm = fmaf(e, e, vm);
            }
            sh_ss[l]   = sqrtf(vs / (float)(ng - 1));
            sh_msum[l] = sqrtf(vm / (float)(ng - 1));
            sh_mn[l]   = mm;
        }
    }
    __syncwarp();

    if (l < 15) {
        float d1 = sh_ss[pi[l]] - sh_ss[pj[l]];
        float d2 = sh_mn[pi[l]] - sh_mn[pj[l]];
        sh_pair[l] = expf(d1 * d1) + expf(d2 * d2);   // MEAN_STD = 1.0
    }
    __syncwarp();

    if (l < G) {
        float subloss = 5e-5f;
        #pragma unroll
        for (int p = 0; p < 15; p++)
            if (pi[p] == l) subloss += sh_pair[p];
        sh_lt[l] = logf(1.0f + sh_msum[l] / (subloss + sh_msum[l]));
    }
    __syncwarp();

    if (l == 0) {
        float loss = 0.f;
        #pragma unroll
        for (int g = 0; g < G; g++) loss += sh_lt[g];
        out[0] = loss;
        g_ctr = 0;   // reset for next graph replay
    }
}

// ---------------------------------------------------------------------------
extern "C" void kernel_launch(void* const* d_in, const int* in_sizes, int n_in,
                              void* d_out, int out_size)
{
    const float* meta1 = (const float*)d_in[0];

    dim3 g1(NC / 1024, NB, ZCH);   // (4, 15, 37) = 2220 CTAs = 3 full waves
    k1_batch_reduce<<<g1, 256>>>(meta1);

    dim3 g2(CC2, NB);              // 240 blocks x 256 threads
    k2_stats_and_loss<<<g2, 256>>>((float*)d_out);
}

// round 6
// speedup vs baseline: 2.4441x; 1.0667x over previous
#include <cuda_runtime.h>
#include <math.h>

#define NB 15
#define NC 4096
#define BATCH 512
#define ZCH 37            // batch chunks in k1: 4*15*37 = 2220 CTAs = 3 exact waves
#define CC2 16            // vec-col chunks in k2: 16*15 = 240 blocks

// Scratch (allocation-free)
__device__ float        g_partial[NB * ZCH * NC];   // [b][z][c]
__device__ float2       g_bpart[NB * CC2];          // per (b, chunk): {sum m, sum m^2}
__device__ unsigned int g_ctr;                      // zero-init; reset by last block

// ---------------------------------------------------------------------------
// Kernel 1: batch-dimension reduction (HBM-bound, reads all 125.8 MB).
// Input is read with __ldcs (evict-first streaming) so the 9.1 MB of partial
// writes stay resident in L2 for kernel 2.
// grid = (NC/1024, NB, ZCH), block = 256, each thread owns one float4 of C
// ---------------------------------------------------------------------------
__global__ void __launch_bounds__(256) k1_batch_reduce(const float* __restrict__ in)
{
    const int b = blockIdx.y;
    const int c = blockIdx.x * 1024 + threadIdx.x * 4;
    const int z = blockIdx.z;

    // uneven split of 512 rows into 37 chunks (31 chunks of 14, 6 of 13)
    const int r0 = (z * BATCH) / ZCH;
    const int r1 = ((z + 1) * BATCH) / ZCH;
    const int n  = r1 - r0;

    const size_t rowstride = (size_t)NB * NC;
    const float4* p = (const float4*)(in + ((size_t)r0 * NB + b) * NC + c);
    const size_t rs4 = rowstride / 4;

    float4 a0 = make_float4(0.f, 0.f, 0.f, 0.f);
    float4 a1 = a0, a2 = a0, a3 = a0;

    int i = 0;
    for (; i + 3 < n; i += 4) {
        float4 v0 = __ldcs(p + (size_t)(i + 0) * rs4);
        float4 v1 = __ldcs(p + (size_t)(i + 1) * rs4);
        float4 v2 = __ldcs(p + (size_t)(i + 2) * rs4);
        float4 v3 = __ldcs(p + (size_t)(i + 3) * rs4);
        a0.x += v0.x; a0.y += v0.y; a0.z += v0.z; a0.w += v0.w;
        a1.x += v1.x; a1.y += v1.y; a1.z += v1.z; a1.w += v1.w;
        a2.x += v2.x; a2.y += v2.y; a2.z += v2.z; a2.w += v2.w;
        a3.x += v3.x; a3.y += v3.y; a3.z += v3.z; a3.w += v3.w;
    }
    for (; i < n; i++) {
        float4 v = __ldcs(p + (size_t)i * rs4);
        a0.x += v.x; a0.y += v.y; a0.z += v.z; a0.w += v.w;
    }

    float4 acc;
    acc.x = (a0.x + a1.x) + (a2.x + a3.x);
    acc.y = (a0.y + a1.y) + (a2.y + a3.y);
    acc.z = (a0.z + a1.z) + (a2.z + a3.z);
    acc.w = (a0.w + a1.w) + (a2.w + a3.w);

    *(float4*)&g_partial[((b * ZCH + z) * NC) + c] = acc;
}

// ---------------------------------------------------------------------------
// Kernel 2 (fused, fp32): grid (CC2, NB) = 240 blocks of 256 threads.
// Threads = 64 c-lanes x 4 z-slices (sizes 10,9,9,9). Each thread issues its
// 9-10 float4 loads independently (full MLP), tree-sums them, smem combines
// z-slices, block reduces (sum m, sum m^2). Last block computes the loss.
// ---------------------------------------------------------------------------
__global__ void __launch_bounds__(256) k2_stats_and_loss(float* __restrict__ out)
{
    const int b     = blockIdx.y;
    const int cc    = blockIdx.x;
    const int tid   = threadIdx.x;
    const int clane = tid & 63;          // 64 vec-columns per block
    const int zsl   = tid >> 6;          // 4 z-slices

    const int c  = (cc * 64 + clane) * 4;            // float index
    const int z0 = (zsl == 0) ? 0 : (1 + 9 * zsl);   // 0,10,19,28 (sizes 10,9,9,9)

    const float4* base = (const float4*)&g_partial[(size_t)(b * ZCH + z0) * NC + c];
    const size_t rs4 = NC / 4;

    // 9 independent loads (+1 for slice 0), then fixed-order tree sum
    float4 v0 = base[0 * rs4];
    float4 v1 = base[1 * rs4];
    float4 v2 = base[2 * rs4];
    float4 v3 = base[3 * rs4];
    float4 v4 = base[4 * rs4];
    float4 v5 = base[5 * rs4];
    float4 v6 = base[6 * rs4];
    float4 v7 = base[7 * rs4];
    float4 v8 = base[8 * rs4];

    float4 t;
    t.x = ((v0.x + v1.x) + (v2.x + v3.x)) + ((v4.x + v5.x) + (v6.x + v7.x)) + v8.x;
    t.y = ((v0.y + v1.y) + (v2.y + v3.y)) + ((v4.y + v5.y) + (v6.y + v7.y)) + v8.y;
    t.z = ((v0.z + v1.z) + (v2.z + v3.z)) + ((v4.z + v5.z) + (v6.z + v7.z)) + v8.z;
    t.w = ((v0.w + v1.w) + (v2.w + v3.w)) + ((v4.w + v5.w) + (v6.w + v7.w)) + v8.w;

    if (zsl == 0) {
        float4 v9 = base[9 * rs4];
        t.x += v9.x; t.y += v9.y; t.z += v9.z; t.w += v9.w;
    }

    __shared__ float4 shz[256];
    shz[tid] = t;
    __syncthreads();

    float s = 0.f, s2 = 0.f;
    if (zsl == 0) {
        float4 u1 = shz[tid + 64], u2 = shz[tid + 128], u3 = shz[tid + 192];
        t.x = (t.x + u1.x) + (u2.x + u3.x);
        t.y = (t.y + u1.y) + (u2.y + u3.y);
        t.z = (t.z + u1.z) + (u2.z + u3.z);
        t.w = (t.w + u1.w) + (u2.w + u3.w);

        const float inv_batch = 1.0f / (float)BATCH;  // exact
        float m0 = t.x * inv_batch;
        float m1 = t.y * inv_batch;
        float m2 = t.z * inv_batch;
        float m3 = t.w * inv_batch;

        s  = (m0 + m1) + (m2 + m3);
        s2 = fmaf(m0, m0, m1 * m1) + fmaf(m2, m2, m3 * m3);

        // warps 0 and 1 are fully covered by tid<64 -> full-warp shuffles OK
        #pragma unroll
        for (int off = 16; off > 0; off >>= 1) {
            s  += __shfl_xor_sync(0xffffffffu, s,  off);
            s2 += __shfl_xor_sync(0xffffffffu, s2, off);
        }
    }

    __shared__ float rs[2], rs2[2];
    if (tid < 64 && (tid & 31) == 0) { rs[tid >> 5] = s; rs2[tid >> 5] = s2; }
    __syncthreads();

    __shared__ int sh_last;
    if (tid == 0) {
        g_bpart[b * CC2 + cc] = make_float2(rs[0] + rs[1], rs2[0] + rs2[1]);
        __threadfence();
        unsigned int old = atomicAdd(&g_ctr, 1u);
        sh_last = (old == NB * CC2 - 1) ? 1 : 0;
    }
    __syncthreads();
    if (!sh_last || tid >= 32) return;

    // ---- last block, warp 0: per-base stats + final loss (all fp32) ----
    __threadfence();   // acquire all blocks' g_bpart

    const int l = tid;
    __shared__ float sh_mean[NB], sh_std[NB];

    if (l < NB) {
        float sum = 0.f, sumsq = 0.f;
        #pragma unroll
        for (int p = 0; p < CC2; p++) {
            float2 v = g_bpart[l * CC2 + p];
            sum += v.x; sumsq += v.y;
        }
        float mean = sum * (1.0f / (float)NC);            // exact scale
        float var  = (sumsq - sum * sum * (1.0f / (float)NC)) * (1.0f / (float)(NC - 1));
        if (var < 0.f) var = 0.f;
        sh_mean[l] = mean;
        sh_std[l]  = sqrtf(var);
    }
    __syncwarp();

    // groups: [0,3) [3,5) [5,6) [6,10) [10,12) [12,15)
    const int starts[7] = {0, 3, 5, 6, 10, 12, 15};
    const int G = 6;
    const int pi[15] = {0,0,0,0,0, 1,1,1,1, 2,2,2, 3,3, 4};
    const int pj[15] = {1,2,3,4,5, 2,3,4,5, 3,4,5, 4,5, 5};

    __shared__ float sh_ss[6], sh_mn[6], sh_msum[6], sh_pair[15], sh_lt[6];

    if (l < G) {
        const int s0 = starts[l], s1 = starts[l + 1];
        const int ng = s1 - s0;
        if (ng == 1) {
            sh_ss[l]   = sh_std[s0];
            sh_msum[l] = sh_mean[s0];
            sh_mn[l]   = sh_mean[s0];
        } else {
            float ms = 0.f, mm = 0.f;
            for (int k = s0; k < s1; k++) { ms += sh_std[k]; mm += sh_mean[k]; }
            ms /= (float)ng; mm /= (float)ng;
            float vs = 0.f, vm = 0.f;
            for (int k = s0; k < s1; k++) {
                float d = sh_std[k]  - ms; vs = fmaf(d, d, vs);
                float e = sh_mean[k] - mm; vm = fmaf(e, e, vm);
            }
            sh_ss[l]   = sqrtf(vs / (float)(ng - 1));
            sh_msum[l] = sqrtf(vm / (float)(ng - 1));
            sh_mn[l]   = mm;
        }
    }
    __syncwarp();

    if (l < 15) {
        float d1 = sh_ss[pi[l]] - sh_ss[pj[l]];
        float d2 = sh_mn[pi[l]] - sh_mn[pj[l]];
        sh_pair[l] = expf(d1 * d1) + expf(d2 * d2);   // MEAN_STD = 1.0
    }
    __syncwarp();

    if (l < G) {
        float subloss = 5e-5f;
        #pragma unroll
        for (int p = 0; p < 15; p++)
            if (pi[p] == l) subloss += sh_pair[p];
        sh_lt[l] = logf(1.0f + sh_msum[l] / (subloss + sh_msum[l]));
    }
    __syncwarp();

    if (l == 0) {
        float loss = 0.f;
        #pragma unroll
        for (int g = 0; g < G; g++) loss += sh_lt[g];
        out[0] = loss;
        g_ctr = 0;   // reset for next graph replay
    }
}

// ---------------------------------------------------------------------------
extern "C" void kernel_launch(void* const* d_in, const int* in_sizes, int n_in,
                              void* d_out, int out_size)
{
    const float* meta1 = (const float*)d_in[0];

    dim3 g1(NC / 1024, NB, ZCH);   // (4, 15, 37) = 2220 CTAs = 3 full waves
    k1_batch_reduce<<<g1, 256>>>(meta1);

    dim3 g2(CC2, NB);              // 240 blocks x 256 threads
    k2_stats_and_loss<<<g2, 256>>>((float*)d_out);
}